// round 1
// baseline (speedup 1.0000x reference)
#include <cuda_runtime.h>
#include <math.h>

#define HID  128
#define NRBF 50
#define MAXE 400000
#define MAXN 25000

// ---- scratch (static __device__ allocations only; no cudaMalloc) ----
__device__ float g_unit[MAXE * 3];
__device__ float g_cut[MAXE];
__device__ float g_dih[MAXE];
__device__ float g_Acol[(size_t)MAXN * 256];   // [node][0:128]=A_c1, [128:256]=A_c2
__device__ float g_Arow[(size_t)MAXN * 256];   // [node][0:128]=A_r1, [128:256]=A_r2
__device__ float g_Wcomb[128 * 640];           // [128][g*128+j], g=0:W_scalar, 1:M_c1, 2:M_r1, 3:M_c2, 4:M_r2
__device__ float g_Rcomb[NRBF * 256];          // [50][256] = W_msg_rbf @ W_vec (both halves)
__device__ float g_cvec[256];                  // b_msg @ W_vec + b_vec
__device__ float g_wsang[128];                 // colsum(W_ang)
__device__ float g_wsdih[128];                 // colsum(W_dih)

__device__ __forceinline__ float sigf(float x) { return 1.f / (1.f + expf(-x)); }

__device__ __forceinline__ void red_add_v4(float* addr, float a, float b, float c, float d) {
    asm volatile("red.global.add.v4.f32 [%0], {%1,%2,%3,%4};"
                 :: "l"(addr), "f"(a), "f"(b), "f"(c), "f"(d) : "memory");
}

// ---------------- weight folding (tiny, runs once per launch) ----------------
__global__ void fold_kernel(const float* __restrict__ Wmsg, const float* __restrict__ bmsg,
                            const float* __restrict__ Wvec, const float* __restrict__ bvec,
                            const float* __restrict__ Wsc,
                            const float* __restrict__ Wang, const float* __restrict__ Wdih) {
    int t = blockIdx.x * blockDim.x + threadIdx.x;
    if (t < 128 * 640) {
        int i = t / 640, cc = t % 640;
        int g = cc >> 7, j = cc & 127;
        float s;
        if (g == 0) {
            s = Wsc[i * 128 + j];
        } else {
            int ri = (g == 2 || g == 4) ? (128 + i) : i;  // rows 0-127: h[col], 128-255: h[row]
            int cj = (g >= 3) ? (128 + j) : j;            // W_vec col half
            s = 0.f;
            const float* wm = Wmsg + (size_t)ri * 128;
            for (int k = 0; k < 128; k++) s += wm[k] * Wvec[k * 256 + cj];
        }
        g_Wcomb[t] = s;
        return;
    }
    t -= 128 * 640;
    if (t < NRBF * 256) {
        int k2 = t / 256, cj = t % 256;
        float s = 0.f;
        const float* wm = Wmsg + (size_t)(256 + k2) * 128;
        for (int k = 0; k < 128; k++) s += wm[k] * Wvec[k * 256 + cj];
        g_Rcomb[t] = s;
        return;
    }
    t -= NRBF * 256;
    if (t < 256) {
        float s = bvec[t];
        for (int k = 0; k < 128; k++) s += bmsg[k] * Wvec[k * 256 + t];
        g_cvec[t] = s;
        return;
    }
    t -= 256;
    if (t < 128) {
        float s = 0.f;
        for (int i = 0; i < 128; i++) s += Wang[i * 128 + t];
        g_wsang[t] = s;
        return;
    }
    t -= 128;
    if (t < 128) {
        float s = 0.f;
        for (int i = 0; i < 128; i++) s += Wdih[i * 128 + t];
        g_wsdih[t] = s;
    }
}

// ---------------- edge geometry: unit vec, cutoff, direction_units scatter ----------------
__global__ void edge_geom_kernel(const float* __restrict__ pos, const int* __restrict__ ei,
                                 int E, float* __restrict__ du) {
    int e = blockIdx.x * blockDim.x + threadIdx.x;
    if (e >= E) return;
    int r = ei[e], c = ei[E + e];
    float dx = pos[3 * c]     - pos[3 * r];
    float dy = pos[3 * c + 1] - pos[3 * r + 1];
    float dz = pos[3 * c + 2] - pos[3 * r + 2];
    float dist = sqrtf(dx * dx + dy * dy + dz * dz) + 1e-8f;
    float inv = 1.f / dist;
    float ux = dx * inv, uy = dy * inv, uz = dz * inv;
    g_unit[3 * e] = ux; g_unit[3 * e + 1] = uy; g_unit[3 * e + 2] = uz;
    float w = 0.f;
    if (dist < 10.f) w = 0.5f * (cosf(3.14159265358979323846f * dist * 0.1f) + 1.f);
    g_cut[e] = w;
    atomicAdd(&du[3 * r],     ux);  atomicAdd(&du[3 * r + 1],  uy);  atomicAdd(&du[3 * r + 2],  uz);
    atomicAdd(&du[3 * c],    -ux);  atomicAdd(&du[3 * c + 1], -uy);  atomicAdd(&du[3 * c + 2], -uz);
}

// ---------------- per-edge dihedral scalar ----------------
__global__ void dih_kernel(const float* __restrict__ du, const int* __restrict__ ei, int E) {
    int e = blockIdx.x * blockDim.x + threadIdx.x;
    if (e >= E) return;
    int r = ei[e], c = ei[E + e];
    float ux = g_unit[3 * e], uy = g_unit[3 * e + 1], uz = g_unit[3 * e + 2];
    float vix = du[3 * r], viy = du[3 * r + 1], viz = du[3 * r + 2];
    float vjx = du[3 * c], vjy = du[3 * c + 1], vjz = du[3 * c + 2];
    float dvi = vix * ux + viy * uy + viz * uz;
    float dvj = vjx * ux + vjy * uy + vjz * uz;
    float ax = vix - dvi * ux, ay = viy - dvi * uy, az = viz - dvi * uz;
    float bx = vjx - dvj * ux, by = vjy - dvj * uy, bz = vjz - dvj * uz;
    g_dih[e] = ax * bx + ay * by + az * bz;
}

// ---------------- node GEMM: h @ [W_scalar | M_c1 | M_r1 | M_c2 | M_r2] ----------------
// grid.y = 0..4 selects output group. BM=64, BN=128, BK=16, 256 threads, 8x4 per thread.
__global__ __launch_bounds__(256) void gemm_node_kernel(
    const float* __restrict__ h, const float* __restrict__ du,
    const float* __restrict__ b_scalar, const float* __restrict__ b_ang,
    float* __restrict__ out_h, float* __restrict__ out_ang, int N) {
    const int g  = blockIdx.y;
    const int m0 = blockIdx.x * 64;
    __shared__ float As[16][64];
    __shared__ __align__(16) float Bs[16][128];
    float acc[8][4];
    #pragma unroll
    for (int i = 0; i < 8; i++)
        #pragma unroll
        for (int j = 0; j < 4; j++) acc[i][j] = 0.f;
    int tid = threadIdx.x;
    int tx = tid & 31, ty = tid >> 5;
    const float* Bp = g_Wcomb + g * 128;
    for (int k0 = 0; k0 < 128; k0 += 16) {
        {
            int m = tid >> 2, kk = (tid & 3) * 4;
            int gm = m0 + m;
            float4 a = make_float4(0.f, 0.f, 0.f, 0.f);
            if (gm < N) a = *(const float4*)(h + (size_t)gm * 128 + k0 + kk);
            As[kk][m] = a.x; As[kk + 1][m] = a.y; As[kk + 2][m] = a.z; As[kk + 3][m] = a.w;
        }
        {
            int rr = tid >> 5, c4 = (tid & 31) * 4;
            *(float4*)&Bs[rr][c4]     = *(const float4*)(Bp + (size_t)(k0 + rr) * 640 + c4);
            *(float4*)&Bs[rr + 8][c4] = *(const float4*)(Bp + (size_t)(k0 + rr + 8) * 640 + c4);
        }
        __syncthreads();
        #pragma unroll
        for (int k = 0; k < 16; k++) {
            float4 b4 = *(const float4*)&Bs[k][tx * 4];
            #pragma unroll
            for (int i = 0; i < 8; i++) {
                float a = As[k][ty * 8 + i];
                acc[i][0] += a * b4.x; acc[i][1] += a * b4.y;
                acc[i][2] += a * b4.z; acc[i][3] += a * b4.w;
            }
        }
        __syncthreads();
    }
    int c = tx * 4;
    if (g == 0) {
        float4 wsa = *(const float4*)&g_wsang[c];
        float4 ba  = *(const float4*)&b_ang[c];
        float4 bs  = *(const float4*)&b_scalar[c];
        #pragma unroll
        for (int i = 0; i < 8; i++) {
            int r = m0 + ty * 8 + i;
            if (r < N) {
                float dx = du[3 * r], dy = du[3 * r + 1], dz = du[3 * r + 2];
                float ang = dx * dx + dy * dy + dz * dz;
                float4 hr = *(const float4*)(h + (size_t)r * 128 + c);
                float4 o;
                o.x = hr.x + (acc[i][0] + bs.x) * sigf(ang * wsa.x + ba.x);
                o.y = hr.y + (acc[i][1] + bs.y) * sigf(ang * wsa.y + ba.y);
                o.z = hr.z + (acc[i][2] + bs.z) * sigf(ang * wsa.z + ba.z);
                o.w = hr.w + (acc[i][3] + bs.w) * sigf(ang * wsa.w + ba.w);
                *(float4*)(out_h   + (size_t)r * 128 + c) = o;
                *(float4*)(out_ang + (size_t)r * 128 + c) = make_float4(ang, ang, ang, ang);
            }
        }
    } else {
        float* dst = (g == 1 || g == 3) ? g_Acol : g_Arow;
        int off = (g >= 3) ? 128 : 0;
        #pragma unroll
        for (int i = 0; i < 8; i++) {
            int r = m0 + ty * 8 + i;
            if (r < N)
                *(float4*)(dst + (size_t)r * 256 + off + c) =
                    make_float4(acc[i][0], acc[i][1], acc[i][2], acc[i][3]);
        }
    }
}

// ---------------- f GEMM: f @ W_edge with dihedral-gate epilogue ----------------
__global__ __launch_bounds__(256) void gemm_f_kernel(
    const float* __restrict__ f, const float* __restrict__ We,
    const float* __restrict__ b_edge, const float* __restrict__ b_dih,
    float* __restrict__ out_f, float* __restrict__ out_dih, int E) {
    const int m0 = blockIdx.x * 64;
    __shared__ float As[16][64];
    __shared__ __align__(16) float Bs[16][128];
    float acc[8][4];
    #pragma unroll
    for (int i = 0; i < 8; i++)
        #pragma unroll
        for (int j = 0; j < 4; j++) acc[i][j] = 0.f;
    int tid = threadIdx.x;
    int tx = tid & 31, ty = tid >> 5;
    for (int k0 = 0; k0 < 128; k0 += 16) {
        {
            int m = tid >> 2, kk = (tid & 3) * 4;
            int gm = m0 + m;
            float4 a = make_float4(0.f, 0.f, 0.f, 0.f);
            if (gm < E) a = *(const float4*)(f + (size_t)gm * 128 + k0 + kk);
            As[kk][m] = a.x; As[kk + 1][m] = a.y; As[kk + 2][m] = a.z; As[kk + 3][m] = a.w;
        }
        {
            int rr = tid >> 5, c4 = (tid & 31) * 4;
            *(float4*)&Bs[rr][c4]     = *(const float4*)(We + (size_t)(k0 + rr) * 128 + c4);
            *(float4*)&Bs[rr + 8][c4] = *(const float4*)(We + (size_t)(k0 + rr + 8) * 128 + c4);
        }
        __syncthreads();
        #pragma unroll
        for (int k = 0; k < 16; k++) {
            float4 b4 = *(const float4*)&Bs[k][tx * 4];
            #pragma unroll
            for (int i = 0; i < 8; i++) {
                float a = As[k][ty * 8 + i];
                acc[i][0] += a * b4.x; acc[i][1] += a * b4.y;
                acc[i][2] += a * b4.z; acc[i][3] += a * b4.w;
            }
        }
        __syncthreads();
    }
    int c = tx * 4;
    float4 wsd = *(const float4*)&g_wsdih[c];
    float4 bd  = *(const float4*)&b_dih[c];
    float4 be  = *(const float4*)&b_edge[c];
    #pragma unroll
    for (int i = 0; i < 8; i++) {
        int r = m0 + ty * 8 + i;
        if (r < E) {
            float dih = g_dih[r];
            float4 fr = *(const float4*)(f + (size_t)r * 128 + c);
            float4 o;
            o.x = fr.x + (acc[i][0] + be.x) * sigf(dih * wsd.x + bd.x);
            o.y = fr.y + (acc[i][1] + be.y) * sigf(dih * wsd.y + bd.y);
            o.z = fr.z + (acc[i][2] + be.z) * sigf(dih * wsd.z + bd.z);
            o.w = fr.w + (acc[i][3] + be.w) * sigf(dih * wsd.w + bd.w);
            *(float4*)(out_f   + (size_t)r * 128 + c) = o;
            *(float4*)(out_dih + (size_t)r * 128 + c) = make_float4(dih, dih, dih, dih);
        }
    }
}

// ---------------- vector message + scatter into v_updated ----------------
// 256 threads: thread t owns column t of (w1|w2). R columns held in registers.
__global__ __launch_bounds__(256) void vec_msg_kernel(
    const float* __restrict__ rbf, const float* __restrict__ v,
    const int* __restrict__ ei, int E, int epb, float* __restrict__ vout) {
    int tid = threadIdx.x;
    float R[NRBF];
    #pragma unroll
    for (int k = 0; k < NRBF; k++) R[k] = g_Rcomb[k * 256 + tid];
    float cb = g_cvec[tid];
    __shared__ __align__(16) float rbf_sh[52];
    __shared__ __align__(16) float wsh[256];
    __shared__ int   s_rc[2];
    __shared__ float s_u[4];
    int e0 = blockIdx.x * epb;
    int e1 = min(e0 + epb, E);
    for (int e = e0; e < e1; e++) {
        if (tid < NRBF) rbf_sh[tid] = rbf[(size_t)e * NRBF + tid];
        if (tid == 64) { s_rc[0] = ei[e]; s_rc[1] = ei[E + e]; }
        if (tid == 96) {
            s_u[0] = g_unit[3 * e]; s_u[1] = g_unit[3 * e + 1];
            s_u[2] = g_unit[3 * e + 2]; s_u[3] = g_cut[e];
        }
        __syncthreads();
        int r = s_rc[0], c = s_rc[1];
        float acc = cb + g_Acol[(size_t)c * 256 + tid] + g_Arow[(size_t)r * 256 + tid];
        #pragma unroll
        for (int k4 = 0; k4 < 48; k4 += 4) {
            float4 q = *(const float4*)&rbf_sh[k4];
            acc += q.x * R[k4] + q.y * R[k4 + 1] + q.z * R[k4 + 2] + q.w * R[k4 + 3];
        }
        acc += rbf_sh[48] * R[48] + rbf_sh[49] * R[49];
        wsh[tid] = acc;
        __syncthreads();
        float cw = s_u[3];
        if (cw != 0.f && tid < 96) {
            int d = tid >> 5;
            int j = (tid & 31) * 4;
            float u = s_u[d];
            float4 w1 = *(const float4*)&wsh[j];
            float4 w2 = *(const float4*)&wsh[128 + j];
            float4 vv = *(const float4*)(v + (size_t)r * 384 + d * 128 + j);
            float m0v = cw * (w1.x * u + w2.x * vv.x);
            float m1v = cw * (w1.y * u + w2.y * vv.y);
            float m2v = cw * (w1.z * u + w2.z * vv.z);
            float m3v = cw * (w1.w * u + w2.w * vv.w);
            red_add_v4(vout + (size_t)c * 384 + d * 128 + j, m0v, m1v, m2v, m3v);
        }
        __syncthreads();
    }
}

extern "C" void kernel_launch(void* const* d_in, const int* in_sizes, int n_in,
                              void* d_out, int out_size) {
    const float* h    = (const float*)d_in[0];
    const float* v    = (const float*)d_in[1];
    const float* f    = (const float*)d_in[2];
    const float* pos  = (const float*)d_in[3];
    const float* rbf  = (const float*)d_in[4];
    const int*   ei   = (const int*)d_in[5];
    const float* Wmsg = (const float*)d_in[6];
    const float* bmsg = (const float*)d_in[7];
    const float* Wvec = (const float*)d_in[8];
    const float* bvec = (const float*)d_in[9];
    const float* Wsc  = (const float*)d_in[10];
    const float* bsc  = (const float*)d_in[11];
    const float* Wed  = (const float*)d_in[12];
    const float* bed  = (const float*)d_in[13];
    const float* bang = (const float*)d_in[15];
    const float* Wang = (const float*)d_in[14];
    const float* Wdih = (const float*)d_in[16];
    const float* bdih = (const float*)d_in[17];

    int N = in_sizes[3] / 3;      // 25000
    int E = in_sizes[5] / 2;      // 400000

    float* out      = (float*)d_out;
    float* out_h    = out;
    float* out_v    = out_h   + (size_t)N * HID;
    float* out_f    = out_v   + (size_t)N * 3 * HID;
    float* out_ang  = out_f   + (size_t)E * HID;
    float* out_dih  = out_ang + (size_t)N * HID;
    float* out_du   = out_dih + (size_t)E * HID;

    // 1. fold weights (tiny)
    int fold_threads = 128 * 640 + NRBF * 256 + 256 + 128 + 128;  // 95232
    fold_kernel<<<(fold_threads + 255) / 256, 256>>>(Wmsg, bmsg, Wvec, bvec, Wsc, Wang, Wdih);

    // 2. zero direction_units, scatter unit vectors
    cudaMemsetAsync(out_du, 0, (size_t)N * 3 * sizeof(float));
    edge_geom_kernel<<<(E + 255) / 256, 256>>>(pos, ei, E, out_du);

    // 3. node GEMM: h_updated + angular_info + A matrices
    gemm_node_kernel<<<dim3((N + 63) / 64, 5), 256>>>(h, out_du, bsc, bang, out_h, out_ang, N);

    // 4. per-edge dihedral scalar
    dih_kernel<<<(E + 255) / 256, 256>>>(out_du, ei, E);

    // 5. f GEMM: f_updated + dihedral_info
    gemm_f_kernel<<<dim3((E + 63) / 64, 1), 256>>>(f, Wed, bed, bdih, out_f, out_dih, E);

    // 6. v_updated = v + scattered vector messages
    cudaMemcpyAsync(out_v, v, (size_t)N * 3 * HID * sizeof(float), cudaMemcpyDeviceToDevice);
    vec_msg_kernel<<<(E + 31) / 32, 256>>>(rbf, v, ei, E, 32, out_v);
}

// round 2
// speedup vs baseline: 1.3784x; 1.3784x over previous
#include <cuda_runtime.h>
#include <math.h>

#define HID  128
#define NRBF 50
#define MAXE 400000
#define MAXN 25000

// ---- scratch (static __device__ allocations only) ----
__device__ float g_unit[MAXE * 3];
__device__ float g_cut[MAXE];
__device__ float g_dih[MAXE];
__device__ float g_Acol[(size_t)MAXN * 256];
__device__ float g_Arow[(size_t)MAXN * 256];
__device__ float g_Wcomb[128 * 640];   // [k][g*128+j] g=0:W_scalar 1:M_c1 2:M_r1 3:M_c2 4:M_r2
__device__ float g_Rcomb[NRBF * 256];
__device__ float g_cvec[256];
__device__ float g_wsang[128];
__device__ float g_wsdih[128];

typedef unsigned long long u64;

__device__ __forceinline__ float sigf(float x) { return 1.f / (1.f + expf(-x)); }

__device__ __forceinline__ void red_add_v4(float* addr, float a, float b, float c, float d) {
    asm volatile("red.global.add.v4.f32 [%0], {%1,%2,%3,%4};"
                 :: "l"(addr), "f"(a), "f"(b), "f"(c), "f"(d) : "memory");
}
__device__ __forceinline__ void ffma2(u64& d, u64 a, u64 b) {
    asm("fma.rn.f32x2 %0, %1, %2, %0;" : "+l"(d) : "l"(a), "l"(b));
}
__device__ __forceinline__ u64 pack2(float x) {
    u64 r; asm("mov.b64 %0, {%1,%1};" : "=l"(r) : "f"(x)); return r;
}
__device__ __forceinline__ u64 packpair(float lo, float hi) {
    u64 r; asm("mov.b64 %0, {%1,%2};" : "=l"(r) : "f"(lo), "f"(hi)); return r;
}
__device__ __forceinline__ void unpack2(u64 p, float& lo, float& hi) {
    asm("mov.b64 {%0,%1}, %2;" : "=f"(lo), "=f"(hi) : "l"(p));
}

// ---------------- weight folding ----------------
__global__ void fold_kernel(const float* __restrict__ Wmsg, const float* __restrict__ bmsg,
                            const float* __restrict__ Wvec, const float* __restrict__ bvec,
                            const float* __restrict__ Wsc,
                            const float* __restrict__ Wang, const float* __restrict__ Wdih) {
    int t = blockIdx.x * blockDim.x + threadIdx.x;
    if (t < 128 * 640) {
        int i = t / 640, cc = t % 640;
        int g = cc >> 7, j = cc & 127;
        float s;
        if (g == 0) {
            s = Wsc[i * 128 + j];
        } else {
            int ri = (g == 2 || g == 4) ? (128 + i) : i;
            int cj = (g >= 3) ? (128 + j) : j;
            s = 0.f;
            const float* wm = Wmsg + (size_t)ri * 128;
            for (int k = 0; k < 128; k++) s += wm[k] * Wvec[k * 256 + cj];
        }
        g_Wcomb[t] = s;
        return;
    }
    t -= 128 * 640;
    if (t < NRBF * 256) {
        int k2 = t / 256, cj = t % 256;
        float s = 0.f;
        const float* wm = Wmsg + (size_t)(256 + k2) * 128;
        for (int k = 0; k < 128; k++) s += wm[k] * Wvec[k * 256 + cj];
        g_Rcomb[t] = s;
        return;
    }
    t -= NRBF * 256;
    if (t < 256) {
        float s = bvec[t];
        for (int k = 0; k < 128; k++) s += bmsg[k] * Wvec[k * 256 + t];
        g_cvec[t] = s;
        return;
    }
    t -= 256;
    if (t < 128) {
        float s = 0.f;
        for (int i = 0; i < 128; i++) s += Wang[i * 128 + t];
        g_wsang[t] = s;
        return;
    }
    t -= 128;
    if (t < 128) {
        float s = 0.f;
        for (int i = 0; i < 128; i++) s += Wdih[i * 128 + t];
        g_wsdih[t] = s;
    }
}

// ---------------- edge geometry ----------------
__global__ void edge_geom_kernel(const float* __restrict__ pos, const int* __restrict__ ei,
                                 int E, float* __restrict__ du) {
    int e = blockIdx.x * blockDim.x + threadIdx.x;
    if (e >= E) return;
    int r = ei[e], c = ei[E + e];
    float dx = pos[3 * c]     - pos[3 * r];
    float dy = pos[3 * c + 1] - pos[3 * r + 1];
    float dz = pos[3 * c + 2] - pos[3 * r + 2];
    float dist = sqrtf(dx * dx + dy * dy + dz * dz) + 1e-8f;
    float inv = 1.f / dist;
    float ux = dx * inv, uy = dy * inv, uz = dz * inv;
    g_unit[3 * e] = ux; g_unit[3 * e + 1] = uy; g_unit[3 * e + 2] = uz;
    float w = 0.f;
    if (dist < 10.f) w = 0.5f * (cosf(3.14159265358979323846f * dist * 0.1f) + 1.f);
    g_cut[e] = w;
    atomicAdd(&du[3 * r],     ux);  atomicAdd(&du[3 * r + 1],  uy);  atomicAdd(&du[3 * r + 2],  uz);
    atomicAdd(&du[3 * c],    -ux);  atomicAdd(&du[3 * c + 1], -uy);  atomicAdd(&du[3 * c + 2], -uz);
}

// ---------------- per-edge dihedral scalar ----------------
__global__ void dih_kernel(const float* __restrict__ du, const int* __restrict__ ei, int E) {
    int e = blockIdx.x * blockDim.x + threadIdx.x;
    if (e >= E) return;
    int r = ei[e], c = ei[E + e];
    float ux = g_unit[3 * e], uy = g_unit[3 * e + 1], uz = g_unit[3 * e + 2];
    float vix = du[3 * r], viy = du[3 * r + 1], viz = du[3 * r + 2];
    float vjx = du[3 * c], vjy = du[3 * c + 1], vjz = du[3 * c + 2];
    float dvi = vix * ux + viy * uy + viz * uz;
    float dvj = vjx * ux + vjy * uy + vjz * uz;
    float ax = vix - dvi * ux, ay = viy - dvi * uy, az = viz - dvi * uz;
    float bx = vjx - dvj * ux, by = vjy - dvj * uy, bz = vjz - dvj * uz;
    g_dih[e] = ax * bx + ay * by + az * bz;
}

// ================= packed-f32x2 GEMM core (BM=128,BN=128,BK=8, 256 thr, 8x8) ============
// acc[i][j] holds packed cols (2j, 2j+1) for row i.
#define GEMM_MAINLOOP(APTR, ALD, BPTR, BLD, ROWGUARD_N)                                    \
    __shared__ __align__(16) float As[8][128];                                             \
    __shared__ __align__(16) float Bs[8][128];                                             \
    u64 acc[8][4];                                                                         \
    _Pragma("unroll")                                                                      \
    for (int i = 0; i < 8; i++) { acc[i][0]=0; acc[i][1]=0; acc[i][2]=0; acc[i][3]=0; }    \
    const int tid = threadIdx.x;                                                           \
    const int tx = tid & 15, ty = tid >> 4;                                                \
    for (int k0 = 0; k0 < 128; k0 += 8) {                                                  \
        {                                                                                  \
            int m = tid >> 1, kk = (tid & 1) * 4;                                          \
            int gm = m0 + m;                                                               \
            float4 a = make_float4(0.f,0.f,0.f,0.f);                                       \
            if (gm < (ROWGUARD_N)) a = *(const float4*)((APTR) + (size_t)gm * (ALD) + k0 + kk); \
            As[kk][m] = a.x; As[kk+1][m] = a.y; As[kk+2][m] = a.z; As[kk+3][m] = a.w;      \
            int kb = tid >> 5, c4 = (tid & 31) * 4;                                        \
            *(float4*)&Bs[kb][c4] = *(const float4*)((BPTR) + (size_t)(k0 + kb) * (BLD) + c4); \
        }                                                                                  \
        __syncthreads();                                                                   \
        _Pragma("unroll")                                                                  \
        for (int k = 0; k < 8; k++) {                                                      \
            float4 a0 = *(const float4*)&As[k][ty * 8];                                    \
            float4 a1 = *(const float4*)&As[k][ty * 8 + 4];                                \
            ulonglong2 b0 = *(const ulonglong2*)&Bs[k][tx * 8];                            \
            ulonglong2 b1 = *(const ulonglong2*)&Bs[k][tx * 8 + 4];                        \
            u64 ap;                                                                        \
            ap = pack2(a0.x); ffma2(acc[0][0],ap,b0.x); ffma2(acc[0][1],ap,b0.y); ffma2(acc[0][2],ap,b1.x); ffma2(acc[0][3],ap,b1.y); \
            ap = pack2(a0.y); ffma2(acc[1][0],ap,b0.x); ffma2(acc[1][1],ap,b0.y); ffma2(acc[1][2],ap,b1.x); ffma2(acc[1][3],ap,b1.y); \
            ap = pack2(a0.z); ffma2(acc[2][0],ap,b0.x); ffma2(acc[2][1],ap,b0.y); ffma2(acc[2][2],ap,b1.x); ffma2(acc[2][3],ap,b1.y); \
            ap = pack2(a0.w); ffma2(acc[3][0],ap,b0.x); ffma2(acc[3][1],ap,b0.y); ffma2(acc[3][2],ap,b1.x); ffma2(acc[3][3],ap,b1.y); \
            ap = pack2(a1.x); ffma2(acc[4][0],ap,b0.x); ffma2(acc[4][1],ap,b0.y); ffma2(acc[4][2],ap,b1.x); ffma2(acc[4][3],ap,b1.y); \
            ap = pack2(a1.y); ffma2(acc[5][0],ap,b0.x); ffma2(acc[5][1],ap,b0.y); ffma2(acc[5][2],ap,b1.x); ffma2(acc[5][3],ap,b1.y); \
            ap = pack2(a1.z); ffma2(acc[6][0],ap,b0.x); ffma2(acc[6][1],ap,b0.y); ffma2(acc[6][2],ap,b1.x); ffma2(acc[6][3],ap,b1.y); \
            ap = pack2(a1.w); ffma2(acc[7][0],ap,b0.x); ffma2(acc[7][1],ap,b0.y); ffma2(acc[7][2],ap,b1.x); ffma2(acc[7][3],ap,b1.y); \
        }                                                                                  \
        __syncthreads();                                                                   \
    }

// ---------------- node GEMM: h @ [W_scalar | M_c1 | M_r1 | M_c2 | M_r2] ----------------
__global__ __launch_bounds__(256) void gemm_node_kernel(
    const float* __restrict__ h, const float* __restrict__ du,
    const float* __restrict__ b_scalar, const float* __restrict__ b_ang,
    float* __restrict__ out_h, float* __restrict__ out_ang, int N) {
    const int g  = blockIdx.y;
    const int m0 = blockIdx.x * 128;
    const float* Bp = g_Wcomb + g * 128;
    GEMM_MAINLOOP(h, 128, Bp, 640, N)

    int c = tx * 8;
    if (g == 0) {
        float4 wsa0 = *(const float4*)&g_wsang[c],  wsa1 = *(const float4*)&g_wsang[c+4];
        float4 ba0  = *(const float4*)&b_ang[c],    ba1  = *(const float4*)&b_ang[c+4];
        float4 bs0  = *(const float4*)&b_scalar[c], bs1  = *(const float4*)&b_scalar[c+4];
        #pragma unroll
        for (int i = 0; i < 8; i++) {
            int r = m0 + ty * 8 + i;
            if (r < N) {
                float dx = du[3*r], dy = du[3*r+1], dz = du[3*r+2];
                float ang = dx*dx + dy*dy + dz*dz;
                float s[8];
                unpack2(acc[i][0], s[0], s[1]); unpack2(acc[i][1], s[2], s[3]);
                unpack2(acc[i][2], s[4], s[5]); unpack2(acc[i][3], s[6], s[7]);
                float4 h0 = *(const float4*)(h + (size_t)r*128 + c);
                float4 h1 = *(const float4*)(h + (size_t)r*128 + c + 4);
                float4 o0, o1;
                o0.x = h0.x + (s[0]+bs0.x)*sigf(ang*wsa0.x+ba0.x);
                o0.y = h0.y + (s[1]+bs0.y)*sigf(ang*wsa0.y+ba0.y);
                o0.z = h0.z + (s[2]+bs0.z)*sigf(ang*wsa0.z+ba0.z);
                o0.w = h0.w + (s[3]+bs0.w)*sigf(ang*wsa0.w+ba0.w);
                o1.x = h1.x + (s[4]+bs1.x)*sigf(ang*wsa1.x+ba1.x);
                o1.y = h1.y + (s[5]+bs1.y)*sigf(ang*wsa1.y+ba1.y);
                o1.z = h1.z + (s[6]+bs1.z)*sigf(ang*wsa1.z+ba1.z);
                o1.w = h1.w + (s[7]+bs1.w)*sigf(ang*wsa1.w+ba1.w);
                *(float4*)(out_h + (size_t)r*128 + c)     = o0;
                *(float4*)(out_h + (size_t)r*128 + c + 4) = o1;
                float4 av = make_float4(ang, ang, ang, ang);
                *(float4*)(out_ang + (size_t)r*128 + c)     = av;
                *(float4*)(out_ang + (size_t)r*128 + c + 4) = av;
            }
        }
    } else {
        float* dst = (g == 1 || g == 3) ? g_Acol : g_Arow;
        int off = (g >= 3) ? 128 : 0;
        #pragma unroll
        for (int i = 0; i < 8; i++) {
            int r = m0 + ty * 8 + i;
            if (r < N) {
                float s[8];
                unpack2(acc[i][0], s[0], s[1]); unpack2(acc[i][1], s[2], s[3]);
                unpack2(acc[i][2], s[4], s[5]); unpack2(acc[i][3], s[6], s[7]);
                *(float4*)(dst + (size_t)r*256 + off + c)     = make_float4(s[0],s[1],s[2],s[3]);
                *(float4*)(dst + (size_t)r*256 + off + c + 4) = make_float4(s[4],s[5],s[6],s[7]);
            }
        }
    }
}

// ---------------- f GEMM: f @ W_edge with dihedral-gate epilogue ----------------
__global__ __launch_bounds__(256) void gemm_f_kernel(
    const float* __restrict__ f, const float* __restrict__ We,
    const float* __restrict__ b_edge, const float* __restrict__ b_dih,
    float* __restrict__ out_f, float* __restrict__ out_dih, int E) {
    const int m0 = blockIdx.x * 128;
    GEMM_MAINLOOP(f, 128, We, 128, E)

    int c = tx * 8;
    float4 wsd0 = *(const float4*)&g_wsdih[c], wsd1 = *(const float4*)&g_wsdih[c+4];
    float4 bd0  = *(const float4*)&b_dih[c],   bd1  = *(const float4*)&b_dih[c+4];
    float4 be0  = *(const float4*)&b_edge[c],  be1  = *(const float4*)&b_edge[c+4];
    #pragma unroll
    for (int i = 0; i < 8; i++) {
        int r = m0 + ty * 8 + i;
        if (r < E) {
            float dih = g_dih[r];
            float s[8];
            unpack2(acc[i][0], s[0], s[1]); unpack2(acc[i][1], s[2], s[3]);
            unpack2(acc[i][2], s[4], s[5]); unpack2(acc[i][3], s[6], s[7]);
            float4 f0 = *(const float4*)(f + (size_t)r*128 + c);
            float4 f1 = *(const float4*)(f + (size_t)r*128 + c + 4);
            float4 o0, o1;
            o0.x = f0.x + (s[0]+be0.x)*sigf(dih*wsd0.x+bd0.x);
            o0.y = f0.y + (s[1]+be0.y)*sigf(dih*wsd0.y+bd0.y);
            o0.z = f0.z + (s[2]+be0.z)*sigf(dih*wsd0.z+bd0.z);
            o0.w = f0.w + (s[3]+be0.w)*sigf(dih*wsd0.w+bd0.w);
            o1.x = f1.x + (s[4]+be1.x)*sigf(dih*wsd1.x+bd1.x);
            o1.y = f1.y + (s[5]+be1.y)*sigf(dih*wsd1.y+bd1.y);
            o1.z = f1.z + (s[6]+be1.z)*sigf(dih*wsd1.z+bd1.z);
            o1.w = f1.w + (s[7]+be1.w)*sigf(dih*wsd1.w+bd1.w);
            *(float4*)(out_f + (size_t)r*128 + c)     = o0;
            *(float4*)(out_f + (size_t)r*128 + c + 4) = o1;
            float4 dv = make_float4(dih, dih, dih, dih);
            *(float4*)(out_dih + (size_t)r*128 + c)     = dv;
            *(float4*)(out_dih + (size_t)r*128 + c + 4) = dv;
        }
    }
}

// ---------------- vector message + scatter, 8 edges per iteration ----------------
// thread t owns column t of (w1|w2); edge pairs packed into f32x2 lanes.
__global__ __launch_bounds__(256) void vec_msg_kernel(
    const float* __restrict__ rbf, const float* __restrict__ v,
    const int* __restrict__ ei, int E, int epb, float* __restrict__ vout) {
    const int tid = threadIdx.x;
    float R[NRBF];
    #pragma unroll
    for (int k = 0; k < NRBF; k++) R[k] = g_Rcomb[k * 256 + tid];
    const float cb = g_cvec[tid];

    __shared__ __align__(16) float rbf_sh[NRBF][8];
    __shared__ __align__(16) float wsh[8][256];
    __shared__ int   s_r[8], s_c[8];
    __shared__ float s_u[8][4];

    const int warp = tid >> 5, lane = tid & 31;
    const int e0b = blockIdx.x * epb;
    const int e1b = min(e0b + epb, E);

    for (int e0 = e0b; e0 < e1b; e0 += 8) {
        // stage rbf (transposed) + edge meta
        for (int idx = tid; idx < 8 * NRBF; idx += 256) {
            int e = idx / NRBF, k = idx - e * NRBF;
            rbf_sh[k][e] = rbf[(size_t)(e0 + e) * NRBF + k];
        }
        if (tid < 8) { s_r[tid] = ei[e0 + tid]; s_c[tid] = ei[E + e0 + tid]; }
        else if (tid < 16) {
            int e = tid - 8;
            s_u[e][0] = g_unit[3*(e0+e)]; s_u[e][1] = g_unit[3*(e0+e)+1];
            s_u[e][2] = g_unit[3*(e0+e)+2]; s_u[e][3] = g_cut[e0+e];
        }
        __syncthreads();

        // per-thread: 4 packed accumulators = 8 edges, column = tid
        u64 acc[4];
        #pragma unroll
        for (int p = 0; p < 4; p++) {
            int ea = 2*p, eb = 2*p + 1;
            float ba = cb + g_Acol[(size_t)s_c[ea]*256 + tid] + g_Arow[(size_t)s_r[ea]*256 + tid];
            float bb = cb + g_Acol[(size_t)s_c[eb]*256 + tid] + g_Arow[(size_t)s_r[eb]*256 + tid];
            acc[p] = packpair(ba, bb);
        }
        #pragma unroll
        for (int k = 0; k < NRBF; k++) {
            u64 rr = pack2(R[k]);
            const u64* rp = (const u64*)&rbf_sh[k][0];
            ffma2(acc[0], rp[0], rr);
            ffma2(acc[1], rp[1], rr);
            ffma2(acc[2], rp[2], rr);
            ffma2(acc[3], rp[3], rr);
        }
        #pragma unroll
        for (int p = 0; p < 4; p++) {
            float lo, hi;
            unpack2(acc[p], lo, hi);
            wsh[2*p][tid] = lo; wsh[2*p+1][tid] = hi;
        }
        __syncthreads();

        // scatter: warp w handles edge w; lane covers 4 columns
        {
            int e = warp;
            float cw = s_u[e][3];
            if (cw != 0.f) {
                int r = s_r[e], c = s_c[e];
                int j = lane * 4;
                float4 w1 = *(const float4*)&wsh[e][j];
                float4 w2 = *(const float4*)&wsh[e][128 + j];
                #pragma unroll
                for (int d = 0; d < 3; d++) {
                    float u = s_u[e][d];
                    float4 vv = *(const float4*)(v + (size_t)r*384 + d*128 + j);
                    red_add_v4(vout + (size_t)c*384 + d*128 + j,
                               cw*(w1.x*u + w2.x*vv.x), cw*(w1.y*u + w2.y*vv.y),
                               cw*(w1.z*u + w2.z*vv.z), cw*(w1.w*u + w2.w*vv.w));
                }
            }
        }
        __syncthreads();
    }
}

extern "C" void kernel_launch(void* const* d_in, const int* in_sizes, int n_in,
                              void* d_out, int out_size) {
    const float* h    = (const float*)d_in[0];
    const float* v    = (const float*)d_in[1];
    const float* f    = (const float*)d_in[2];
    const float* pos  = (const float*)d_in[3];
    const float* rbf  = (const float*)d_in[4];
    const int*   ei   = (const int*)d_in[5];
    const float* Wmsg = (const float*)d_in[6];
    const float* bmsg = (const float*)d_in[7];
    const float* Wvec = (const float*)d_in[8];
    const float* bvec = (const float*)d_in[9];
    const float* Wsc  = (const float*)d_in[10];
    const float* bsc  = (const float*)d_in[11];
    const float* Wed  = (const float*)d_in[12];
    const float* bed  = (const float*)d_in[13];
    const float* Wang = (const float*)d_in[14];
    const float* bang = (const float*)d_in[15];
    const float* Wdih = (const float*)d_in[16];
    const float* bdih = (const float*)d_in[17];

    int N = in_sizes[3] / 3;
    int E = in_sizes[5] / 2;

    float* out      = (float*)d_out;
    float* out_h    = out;
    float* out_v    = out_h   + (size_t)N * HID;
    float* out_f    = out_v   + (size_t)N * 3 * HID;
    float* out_ang  = out_f   + (size_t)E * HID;
    float* out_dih  = out_ang + (size_t)N * HID;
    float* out_du   = out_dih + (size_t)E * HID;

    int fold_threads = 128 * 640 + NRBF * 256 + 256 + 128 + 128;
    fold_kernel<<<(fold_threads + 255) / 256, 256>>>(Wmsg, bmsg, Wvec, bvec, Wsc, Wang, Wdih);

    cudaMemsetAsync(out_du, 0, (size_t)N * 3 * sizeof(float));
    edge_geom_kernel<<<(E + 255) / 256, 256>>>(pos, ei, E, out_du);

    gemm_node_kernel<<<dim3((N + 127) / 128, 5), 256>>>(h, out_du, bsc, bang, out_h, out_ang, N);

    dih_kernel<<<(E + 255) / 256, 256>>>(out_du, ei, E);

    gemm_f_kernel<<<dim3((E + 127) / 128, 1), 256>>>(f, Wed, bed, bdih, out_f, out_dih, E);

    cudaMemcpyAsync(out_v, v, (size_t)N * 3 * HID * sizeof(float), cudaMemcpyDeviceToDevice);
    vec_msg_kernel<<<(E + 31) / 32, 256>>>(rbf, v, ei, E, 32, out_v);
}

// round 3
// speedup vs baseline: 1.4147x; 1.0263x over previous
#include <cuda_runtime.h>
#include <math.h>

#define HID  128
#define NRBF 50
#define MAXE 400000
#define MAXN 25000

// ---- scratch (static __device__ allocations only) ----
__device__ float g_unit[MAXE * 3];
__device__ float g_cut[MAXE];
__device__ float g_dih[MAXE];
__device__ float g_Acol[(size_t)MAXN * 256];
__device__ float g_Arow[(size_t)MAXN * 256];
__device__ float g_T[307 * 256];        // [Wmsg;bmsg] @ Wvec
__device__ float g_wsang[128];
__device__ float g_wsdih[128];

typedef unsigned long long u64;

__device__ __forceinline__ float sigf(float x) { return 1.f / (1.f + expf(-x)); }

__device__ __forceinline__ void red_add_v4(float* addr, float a, float b, float c, float d) {
    asm volatile("red.global.add.v4.f32 [%0], {%1,%2,%3,%4};"
                 :: "l"(addr), "f"(a), "f"(b), "f"(c), "f"(d) : "memory");
}
__device__ __forceinline__ void ffma2(u64& d, u64 a, u64 b) {
    asm("fma.rn.f32x2 %0, %1, %2, %0;" : "+l"(d) : "l"(a), "l"(b));
}
__device__ __forceinline__ u64 pack2(float x) {
    u64 r; asm("mov.b64 %0, {%1,%1};" : "=l"(r) : "f"(x)); return r;
}
__device__ __forceinline__ u64 packpair(float lo, float hi) {
    u64 r; asm("mov.b64 %0, {%1,%2};" : "=l"(r) : "f"(lo), "f"(hi)); return r;
}
__device__ __forceinline__ void unpack2(u64 p, float& lo, float& hi) {
    asm("mov.b64 {%0,%1}, %2;" : "=f"(lo), "=f"(hi) : "l"(p));
}

// ================= packed-f32x2 GEMM inner product step =================
#define GEMM_INNER8()                                                                      \
    _Pragma("unroll")                                                                      \
    for (int k = 0; k < 8; k++) {                                                          \
        float4 a0 = *(const float4*)&As[k][ty * 8];                                        \
        float4 a1 = *(const float4*)&As[k][ty * 8 + 4];                                    \
        ulonglong2 b0 = *(const ulonglong2*)&Bs[k][tx * 8];                                \
        ulonglong2 b1 = *(const ulonglong2*)&Bs[k][tx * 8 + 4];                            \
        u64 ap;                                                                            \
        ap = pack2(a0.x); ffma2(acc[0][0],ap,b0.x); ffma2(acc[0][1],ap,b0.y); ffma2(acc[0][2],ap,b1.x); ffma2(acc[0][3],ap,b1.y); \
        ap = pack2(a0.y); ffma2(acc[1][0],ap,b0.x); ffma2(acc[1][1],ap,b0.y); ffma2(acc[1][2],ap,b1.x); ffma2(acc[1][3],ap,b1.y); \
        ap = pack2(a0.z); ffma2(acc[2][0],ap,b0.x); ffma2(acc[2][1],ap,b0.y); ffma2(acc[2][2],ap,b1.x); ffma2(acc[2][3],ap,b1.y); \
        ap = pack2(a0.w); ffma2(acc[3][0],ap,b0.x); ffma2(acc[3][1],ap,b0.y); ffma2(acc[3][2],ap,b1.x); ffma2(acc[3][3],ap,b1.y); \
        ap = pack2(a1.x); ffma2(acc[4][0],ap,b0.x); ffma2(acc[4][1],ap,b0.y); ffma2(acc[4][2],ap,b1.x); ffma2(acc[4][3],ap,b1.y); \
        ap = pack2(a1.y); ffma2(acc[5][0],ap,b0.x); ffma2(acc[5][1],ap,b0.y); ffma2(acc[5][2],ap,b1.x); ffma2(acc[5][3],ap,b1.y); \
        ap = pack2(a1.z); ffma2(acc[6][0],ap,b0.x); ffma2(acc[6][1],ap,b0.y); ffma2(acc[6][2],ap,b1.x); ffma2(acc[6][3],ap,b1.y); \
        ap = pack2(a1.w); ffma2(acc[7][0],ap,b0.x); ffma2(acc[7][1],ap,b0.y); ffma2(acc[7][2],ap,b1.x); ffma2(acc[7][3],ap,b1.y); \
    }

#define GEMM_MAINLOOP(APTR, ALD, BPTR, BLD, ROWGUARD_N)                                    \
    __shared__ __align__(16) float As[8][128];                                             \
    __shared__ __align__(16) float Bs[8][128];                                             \
    u64 acc[8][4];                                                                         \
    _Pragma("unroll")                                                                      \
    for (int i = 0; i < 8; i++) { acc[i][0]=0; acc[i][1]=0; acc[i][2]=0; acc[i][3]=0; }    \
    const int tid = threadIdx.x;                                                           \
    const int tx = tid & 15, ty = tid >> 4;                                                \
    for (int k0 = 0; k0 < 128; k0 += 8) {                                                  \
        {                                                                                  \
            int m = tid >> 1, kk = (tid & 1) * 4;                                          \
            int gm = m0 + m;                                                               \
            float4 a = make_float4(0.f,0.f,0.f,0.f);                                       \
            if (gm < (ROWGUARD_N)) a = *(const float4*)((APTR) + (size_t)gm * (ALD) + k0 + kk); \
            As[kk][m] = a.x; As[kk+1][m] = a.y; As[kk+2][m] = a.z; As[kk+3][m] = a.w;      \
            int kb = tid >> 5, c4 = (tid & 31) * 4;                                        \
            *(float4*)&Bs[kb][c4] = *(const float4*)((BPTR) + (size_t)(k0 + kb) * (BLD) + c4); \
        }                                                                                  \
        __syncthreads();                                                                   \
        GEMM_INNER8()                                                                      \
        __syncthreads();                                                                   \
    }

// ---------------- foldT: T = [Wmsg(306x128); bmsg] @ Wvec(128x256) ----------------
__global__ __launch_bounds__(256) void foldT_kernel(
    const float* __restrict__ Wmsg, const float* __restrict__ bmsg,
    const float* __restrict__ Wvec) {
    const int m0 = blockIdx.x * 128;
    const int n0 = blockIdx.y * 128;
    __shared__ __align__(16) float As[8][128];
    __shared__ __align__(16) float Bs[8][128];
    u64 acc[8][4];
    #pragma unroll
    for (int i = 0; i < 8; i++) { acc[i][0]=0; acc[i][1]=0; acc[i][2]=0; acc[i][3]=0; }
    const int tid = threadIdx.x;
    const int tx = tid & 15, ty = tid >> 4;
    for (int k0 = 0; k0 < 128; k0 += 8) {
        {
            int m = tid >> 1, kk = (tid & 1) * 4;
            int gm = m0 + m;
            float4 a = make_float4(0.f,0.f,0.f,0.f);
            if (gm < 306)       a = *(const float4*)(Wmsg + (size_t)gm * 128 + k0 + kk);
            else if (gm == 306) a = *(const float4*)(bmsg + k0 + kk);
            As[kk][m] = a.x; As[kk+1][m] = a.y; As[kk+2][m] = a.z; As[kk+3][m] = a.w;
            int kb = tid >> 5, c4 = (tid & 31) * 4;
            *(float4*)&Bs[kb][c4] = *(const float4*)(Wvec + (size_t)(k0 + kb) * 256 + n0 + c4);
        }
        __syncthreads();
        GEMM_INNER8()
        __syncthreads();
    }
    int c = tx * 8;
    #pragma unroll
    for (int i = 0; i < 8; i++) {
        int r = m0 + ty * 8 + i;
        if (r < 307) {
            float s[8];
            unpack2(acc[i][0], s[0], s[1]); unpack2(acc[i][1], s[2], s[3]);
            unpack2(acc[i][2], s[4], s[5]); unpack2(acc[i][3], s[6], s[7]);
            *(float4*)(g_T + (size_t)r*256 + n0 + c)     = make_float4(s[0],s[1],s[2],s[3]);
            *(float4*)(g_T + (size_t)r*256 + n0 + c + 4) = make_float4(s[4],s[5],s[6],s[7]);
        }
    }
}

// ---------------- aux: column sums of W_ang, W_dih ----------------
__global__ void aux_kernel(const float* __restrict__ Wang, const float* __restrict__ Wdih) {
    int t = threadIdx.x;
    if (t < 128) {
        float s = 0.f;
        for (int i = 0; i < 128; i++) s += Wang[i * 128 + t];
        g_wsang[t] = s;
    } else {
        int j = t - 128;
        float s = 0.f;
        for (int i = 0; i < 128; i++) s += Wdih[i * 128 + j];
        g_wsdih[j] = s;
    }
}

// ---------------- edge geometry ----------------
__global__ void edge_geom_kernel(const float* __restrict__ pos, const int* __restrict__ ei,
                                 int E, float* __restrict__ du) {
    int e = blockIdx.x * blockDim.x + threadIdx.x;
    if (e >= E) return;
    int r = ei[e], c = ei[E + e];
    float dx = pos[3 * c]     - pos[3 * r];
    float dy = pos[3 * c + 1] - pos[3 * r + 1];
    float dz = pos[3 * c + 2] - pos[3 * r + 2];
    float dist = sqrtf(dx * dx + dy * dy + dz * dz) + 1e-8f;
    float inv = 1.f / dist;
    float ux = dx * inv, uy = dy * inv, uz = dz * inv;
    g_unit[3 * e] = ux; g_unit[3 * e + 1] = uy; g_unit[3 * e + 2] = uz;
    float w = 0.f;
    if (dist < 10.f) w = 0.5f * (cosf(3.14159265358979323846f * dist * 0.1f) + 1.f);
    g_cut[e] = w;
    atomicAdd(&du[3 * r],     ux);  atomicAdd(&du[3 * r + 1],  uy);  atomicAdd(&du[3 * r + 2],  uz);
    atomicAdd(&du[3 * c],    -ux);  atomicAdd(&du[3 * c + 1], -uy);  atomicAdd(&du[3 * c + 2], -uz);
}

// ---------------- per-edge dihedral scalar ----------------
__global__ void dih_kernel(const float* __restrict__ du, const int* __restrict__ ei, int E) {
    int e = blockIdx.x * blockDim.x + threadIdx.x;
    if (e >= E) return;
    int r = ei[e], c = ei[E + e];
    float ux = g_unit[3 * e], uy = g_unit[3 * e + 1], uz = g_unit[3 * e + 2];
    float vix = du[3 * r], viy = du[3 * r + 1], viz = du[3 * r + 2];
    float vjx = du[3 * c], vjy = du[3 * c + 1], vjz = du[3 * c + 2];
    float dvi = vix * ux + viy * uy + viz * uz;
    float dvj = vjx * ux + vjy * uy + vjz * uz;
    float ax = vix - dvi * ux, ay = viy - dvi * uy, az = viz - dvi * uz;
    float bx = vjx - dvj * ux, by = vjy - dvj * uy, bz = vjz - dvj * uz;
    g_dih[e] = ax * bx + ay * by + az * bz;
}

// ---------------- node GEMM: h @ {W_scalar | T slices} ----------------
__global__ __launch_bounds__(256) void gemm_node_kernel(
    const float* __restrict__ h, const float* __restrict__ du,
    const float* __restrict__ Wsc,
    const float* __restrict__ b_scalar, const float* __restrict__ b_ang,
    float* __restrict__ out_h, float* __restrict__ out_ang, int N) {
    const int g  = blockIdx.y;
    const int m0 = blockIdx.x * 128;
    const float* Bp; int bld;
    if      (g == 0) { Bp = Wsc;                 bld = 128; }
    else if (g == 1) { Bp = g_T;                 bld = 256; }  // M_c1
    else if (g == 2) { Bp = g_T + 128*256;       bld = 256; }  // M_r1
    else if (g == 3) { Bp = g_T + 128;           bld = 256; }  // M_c2
    else             { Bp = g_T + 128*256 + 128; bld = 256; }  // M_r2
    GEMM_MAINLOOP(h, 128, Bp, bld, N)

    int c = tx * 8;
    if (g == 0) {
        float4 wsa0 = *(const float4*)&g_wsang[c],  wsa1 = *(const float4*)&g_wsang[c+4];
        float4 ba0  = *(const float4*)&b_ang[c],    ba1  = *(const float4*)&b_ang[c+4];
        float4 bs0  = *(const float4*)&b_scalar[c], bs1  = *(const float4*)&b_scalar[c+4];
        #pragma unroll
        for (int i = 0; i < 8; i++) {
            int r = m0 + ty * 8 + i;
            if (r < N) {
                float dx = du[3*r], dy = du[3*r+1], dz = du[3*r+2];
                float ang = dx*dx + dy*dy + dz*dz;
                float s[8];
                unpack2(acc[i][0], s[0], s[1]); unpack2(acc[i][1], s[2], s[3]);
                unpack2(acc[i][2], s[4], s[5]); unpack2(acc[i][3], s[6], s[7]);
                float4 h0 = *(const float4*)(h + (size_t)r*128 + c);
                float4 h1 = *(const float4*)(h + (size_t)r*128 + c + 4);
                float4 o0, o1;
                o0.x = h0.x + (s[0]+bs0.x)*sigf(ang*wsa0.x+ba0.x);
                o0.y = h0.y + (s[1]+bs0.y)*sigf(ang*wsa0.y+ba0.y);
                o0.z = h0.z + (s[2]+bs0.z)*sigf(ang*wsa0.z+ba0.z);
                o0.w = h0.w + (s[3]+bs0.w)*sigf(ang*wsa0.w+ba0.w);
                o1.x = h1.x + (s[4]+bs1.x)*sigf(ang*wsa1.x+ba1.x);
                o1.y = h1.y + (s[5]+bs1.y)*sigf(ang*wsa1.y+ba1.y);
                o1.z = h1.z + (s[6]+bs1.z)*sigf(ang*wsa1.z+ba1.z);
                o1.w = h1.w + (s[7]+bs1.w)*sigf(ang*wsa1.w+ba1.w);
                *(float4*)(out_h + (size_t)r*128 + c)     = o0;
                *(float4*)(out_h + (size_t)r*128 + c + 4) = o1;
                float4 av = make_float4(ang, ang, ang, ang);
                *(float4*)(out_ang + (size_t)r*128 + c)     = av;
                *(float4*)(out_ang + (size_t)r*128 + c + 4) = av;
            }
        }
    } else {
        float* dst = (g == 1 || g == 3) ? g_Acol : g_Arow;
        int off = (g >= 3) ? 128 : 0;
        #pragma unroll
        for (int i = 0; i < 8; i++) {
            int r = m0 + ty * 8 + i;
            if (r < N) {
                float s[8];
                unpack2(acc[i][0], s[0], s[1]); unpack2(acc[i][1], s[2], s[3]);
                unpack2(acc[i][2], s[4], s[5]); unpack2(acc[i][3], s[6], s[7]);
                *(float4*)(dst + (size_t)r*256 + off + c)     = make_float4(s[0],s[1],s[2],s[3]);
                *(float4*)(dst + (size_t)r*256 + off + c + 4) = make_float4(s[4],s[5],s[6],s[7]);
            }
        }
    }
}

// ---------------- f GEMM: f @ W_edge with dihedral-gate epilogue ----------------
__global__ __launch_bounds__(256) void gemm_f_kernel(
    const float* __restrict__ f, const float* __restrict__ We,
    const float* __restrict__ b_edge, const float* __restrict__ b_dih,
    float* __restrict__ out_f, float* __restrict__ out_dih, int E) {
    const int m0 = blockIdx.x * 128;
    GEMM_MAINLOOP(f, 128, We, 128, E)

    int c = tx * 8;
    float4 wsd0 = *(const float4*)&g_wsdih[c], wsd1 = *(const float4*)&g_wsdih[c+4];
    float4 bd0  = *(const float4*)&b_dih[c],   bd1  = *(const float4*)&b_dih[c+4];
    float4 be0  = *(const float4*)&b_edge[c],  be1  = *(const float4*)&b_edge[c+4];
    #pragma unroll
    for (int i = 0; i < 8; i++) {
        int r = m0 + ty * 8 + i;
        if (r < E) {
            float dih = g_dih[r];
            float s[8];
            unpack2(acc[i][0], s[0], s[1]); unpack2(acc[i][1], s[2], s[3]);
            unpack2(acc[i][2], s[4], s[5]); unpack2(acc[i][3], s[6], s[7]);
            float4 f0 = *(const float4*)(f + (size_t)r*128 + c);
            float4 f1 = *(const float4*)(f + (size_t)r*128 + c + 4);
            float4 o0, o1;
            o0.x = f0.x + (s[0]+be0.x)*sigf(dih*wsd0.x+bd0.x);
            o0.y = f0.y + (s[1]+be0.y)*sigf(dih*wsd0.y+bd0.y);
            o0.z = f0.z + (s[2]+be0.z)*sigf(dih*wsd0.z+bd0.z);
            o0.w = f0.w + (s[3]+be0.w)*sigf(dih*wsd0.w+bd0.w);
            o1.x = f1.x + (s[4]+be1.x)*sigf(dih*wsd1.x+bd1.x);
            o1.y = f1.y + (s[5]+be1.y)*sigf(dih*wsd1.y+bd1.y);
            o1.z = f1.z + (s[6]+be1.z)*sigf(dih*wsd1.z+bd1.z);
            o1.w = f1.w + (s[7]+be1.w)*sigf(dih*wsd1.w+bd1.w);
            *(float4*)(out_f + (size_t)r*128 + c)     = o0;
            *(float4*)(out_f + (size_t)r*128 + c + 4) = o1;
            float4 dv = make_float4(dih, dih, dih, dih);
            *(float4*)(out_dih + (size_t)r*128 + c)     = dv;
            *(float4*)(out_dih + (size_t)r*128 + c + 4) = dv;
        }
    }
}

// ---------------- vector message + scatter, 8 edges per iteration ----------------
__global__ __launch_bounds__(256) void vec_msg_kernel(
    const float* __restrict__ rbf, const float* __restrict__ v,
    const float* __restrict__ bvec,
    const int* __restrict__ ei, int E, int epb, float* __restrict__ vout) {
    const int tid = threadIdx.x;
    float R[NRBF];
    #pragma unroll
    for (int k = 0; k < NRBF; k++) R[k] = g_T[(size_t)(256 + k) * 256 + tid];
    const float cb = g_T[(size_t)306 * 256 + tid] + bvec[tid];

    __shared__ __align__(16) float rbf_sh[NRBF][8];
    __shared__ __align__(16) float wsh[8][256];
    __shared__ int   s_r[8], s_c[8];
    __shared__ float s_u[8][4];

    const int warp = tid >> 5, lane = tid & 31;
    const int e0b = blockIdx.x * epb;
    const int e1b = min(e0b + epb, E);

    for (int e0 = e0b; e0 < e1b; e0 += 8) {
        for (int idx = tid; idx < 8 * NRBF; idx += 256) {
            int e = idx / NRBF, k = idx - e * NRBF;
            rbf_sh[k][e] = (e0 + e < E) ? rbf[(size_t)(e0 + e) * NRBF + k] : 0.f;
        }
        if (tid < 8) {
            int ok = (e0 + tid < E);
            s_r[tid] = ok ? ei[e0 + tid] : 0;
            s_c[tid] = ok ? ei[E + e0 + tid] : 0;
        } else if (tid < 16) {
            int e = tid - 8;
            if (e0 + e < E) {
                s_u[e][0] = g_unit[3*(e0+e)]; s_u[e][1] = g_unit[3*(e0+e)+1];
                s_u[e][2] = g_unit[3*(e0+e)+2]; s_u[e][3] = g_cut[e0+e];
            } else {
                s_u[e][0] = s_u[e][1] = s_u[e][2] = s_u[e][3] = 0.f;
            }
        }
        __syncthreads();

        u64 acc[4];
        #pragma unroll
        for (int p = 0; p < 4; p++) {
            int ea = 2*p, eb = 2*p + 1;
            float ba = cb + g_Acol[(size_t)s_c[ea]*256 + tid] + g_Arow[(size_t)s_r[ea]*256 + tid];
            float bb = cb + g_Acol[(size_t)s_c[eb]*256 + tid] + g_Arow[(size_t)s_r[eb]*256 + tid];
            acc[p] = packpair(ba, bb);
        }
        #pragma unroll
        for (int k = 0; k < NRBF; k++) {
            u64 rr = pack2(R[k]);
            const u64* rp = (const u64*)&rbf_sh[k][0];
            ffma2(acc[0], rp[0], rr);
            ffma2(acc[1], rp[1], rr);
            ffma2(acc[2], rp[2], rr);
            ffma2(acc[3], rp[3], rr);
        }
        #pragma unroll
        for (int p = 0; p < 4; p++) {
            float lo, hi;
            unpack2(acc[p], lo, hi);
            wsh[2*p][tid] = lo; wsh[2*p+1][tid] = hi;
        }
        __syncthreads();

        {
            int e = warp;
            float cw = s_u[e][3];
            if (cw != 0.f) {
                int r = s_r[e], c = s_c[e];
                int j = lane * 4;
                float4 w1 = *(const float4*)&wsh[e][j];
                float4 w2 = *(const float4*)&wsh[e][128 + j];
                #pragma unroll
                for (int d = 0; d < 3; d++) {
                    float u = s_u[e][d];
                    float4 vv = *(const float4*)(v + (size_t)r*384 + d*128 + j);
                    red_add_v4(vout + (size_t)c*384 + d*128 + j,
                               cw*(w1.x*u + w2.x*vv.x), cw*(w1.y*u + w2.y*vv.y),
                               cw*(w1.z*u + w2.z*vv.z), cw*(w1.w*u + w2.w*vv.w));
                }
            }
        }
        __syncthreads();
    }
}

extern "C" void kernel_launch(void* const* d_in, const int* in_sizes, int n_in,
                              void* d_out, int out_size) {
    const float* h    = (const float*)d_in[0];
    const float* v    = (const float*)d_in[1];
    const float* f    = (const float*)d_in[2];
    const float* pos  = (const float*)d_in[3];
    const float* rbf  = (const float*)d_in[4];
    const int*   ei   = (const int*)d_in[5];
    const float* Wmsg = (const float*)d_in[6];
    const float* bmsg = (const float*)d_in[7];
    const float* Wvec = (const float*)d_in[8];
    const float* bvec = (const float*)d_in[9];
    const float* Wsc  = (const float*)d_in[10];
    const float* bsc  = (const float*)d_in[11];
    const float* Wed  = (const float*)d_in[12];
    const float* bed  = (const float*)d_in[13];
    const float* Wang = (const float*)d_in[14];
    const float* bang = (const float*)d_in[15];
    const float* Wdih = (const float*)d_in[16];
    const float* bdih = (const float*)d_in[17];

    int N = in_sizes[3] / 3;
    int E = in_sizes[5] / 2;

    float* out      = (float*)d_out;
    float* out_h    = out;
    float* out_v    = out_h   + (size_t)N * HID;
    float* out_f    = out_v   + (size_t)N * 3 * HID;
    float* out_ang  = out_f   + (size_t)E * HID;
    float* out_dih  = out_ang + (size_t)N * HID;
    float* out_du   = out_dih + (size_t)E * HID;

    static cudaStream_t s1 = nullptr, s2 = nullptr;
    static cudaEvent_t ev_root, ev_fold, ev_geo, ev_cpy, ev_s1;
    if (!s1) {
        cudaStreamCreateWithFlags(&s1, cudaStreamNonBlocking);
        cudaStreamCreateWithFlags(&s2, cudaStreamNonBlocking);
        cudaEventCreateWithFlags(&ev_root, cudaEventDisableTiming);
        cudaEventCreateWithFlags(&ev_fold, cudaEventDisableTiming);
        cudaEventCreateWithFlags(&ev_geo,  cudaEventDisableTiming);
        cudaEventCreateWithFlags(&ev_cpy,  cudaEventDisableTiming);
        cudaEventCreateWithFlags(&ev_s1,   cudaEventDisableTiming);
    }

    // fork side streams off the capture (default) stream
    cudaEventRecord(ev_root, 0);
    cudaStreamWaitEvent(s1, ev_root, 0);
    cudaStreamWaitEvent(s2, ev_root, 0);

    // s2: v copy (independent)
    cudaMemcpyAsync(out_v, v, (size_t)N * 3 * HID * sizeof(float),
                    cudaMemcpyDeviceToDevice, s2);
    cudaEventRecord(ev_cpy, s2);

    // s1: fold chain
    foldT_kernel<<<dim3(3, 2), 256, 0, s1>>>(Wmsg, bmsg, Wvec);
    aux_kernel<<<1, 256, 0, s1>>>(Wang, Wdih);
    cudaEventRecord(ev_fold, s1);

    // stream0: geometry chain
    cudaMemsetAsync(out_du, 0, (size_t)N * 3 * sizeof(float), 0);
    edge_geom_kernel<<<(E + 255) / 256, 256, 0, 0>>>(pos, ei, E, out_du);
    cudaEventRecord(ev_geo, 0);

    // s1: dih + f-GEMM (needs geom + fold; fold already ordered on s1)
    cudaStreamWaitEvent(s1, ev_geo, 0);
    dih_kernel<<<(E + 255) / 256, 256, 0, s1>>>(out_du, ei, E);
    gemm_f_kernel<<<dim3((E + 127) / 128, 1), 256, 0, s1>>>(f, Wed, bed, bdih, out_f, out_dih, E);
    cudaEventRecord(ev_s1, s1);

    // stream0: node GEMM (needs fold + geom) then vec_msg (needs node GEMM + v copy)
    cudaStreamWaitEvent(0, ev_fold, 0);
    gemm_node_kernel<<<dim3((N + 127) / 128, 5), 256, 0, 0>>>(h, out_du, Wsc, bsc, bang,
                                                              out_h, out_ang, N);
    cudaStreamWaitEvent(0, ev_cpy, 0);
    const int EPB = 96;
    vec_msg_kernel<<<(E + EPB - 1) / EPB, 256, 0, 0>>>(rbf, v, bvec, ei, E, EPB, out_v);

    // join
    cudaStreamWaitEvent(0, ev_s1, 0);
}